// round 16
// baseline (speedup 1.0000x reference)
#include <cuda_runtime.h>
#include <cuda_bf16.h>
#include <mma.h>
#include <math.h>
#include <stdint.h>

using namespace nvcuda;

static constexpr int M0 = 32768;     // B*N nodes at layer 0
static constexpr int E0 = 262144;    // edges
static constexpr int CAP = 96;       // bucket capacity
static constexpr int CNT_TOT = M0 + M0 / 2 + M0 / 4;
static constexpr int BM0_WORDS = (16384 * 512) / 32;
static constexpr int BM1_WORDS = (8192 * 256) / 32;
static constexpr int BM_TOT = BM0_WORDS + BM1_WORDS;

// ---------------- device scratch ----------------
__device__ float g_h[M0 * 128];
__device__ float g_x[(M0 / 2) * 128];
__device__ float g_es[M0];
__device__ float g_ed[M0];
__device__ int g_adj[CNT_TOT * CAP];
__device__ int g_cnt[CNT_TOT];
__device__ unsigned g_bitmap[BM_TOT];
__device__ float g_sum[3][128];
__device__ float g_sumsq[3][128];
__device__ __align__(16) __nv_bfloat16 g_whi[2][128 * 128];   // pre-split W1, W2
__device__ __align__(16) __nv_bfloat16 g_wlo[2][128 * 128];

__device__ __forceinline__ float lrelu(float x) { return x > 0.f ? x : 0.2f * x; }

// ---------------- setup ----------------

// stream A: zero layer-0 counters + BN stat slots
__global__ void clearA_kernel() {
    int i = blockIdx.x * blockDim.x + threadIdx.x;
    if (i < M0) g_cnt[i] = 0;
    if (i < 3 * 128) { (&g_sum[0][0])[i] = 0.f; (&g_sumsq[0][0])[i] = 0.f; }
}

// stream B: zero bitmaps + layer-1/2 counters
__global__ void clearB_kernel() {
    int i = blockIdx.x * blockDim.x + threadIdx.x;
    if (i < BM_TOT) g_bitmap[i] = 0u;
    if (i < CNT_TOT - M0) g_cnt[M0 + i] = 0;
}

__global__ void wsplit_kernel(const float* __restrict__ W,
                              __nv_bfloat16* __restrict__ hi,
                              __nv_bfloat16* __restrict__ lo) {
    int i = blockIdx.x * blockDim.x + threadIdx.x;   // 0..16383
    float v = W[i];
    __nv_bfloat16 h = __float2bfloat16(v);
    hi[i] = h;
    lo[i] = __float2bfloat16(v - __bfloat162float(h));
}

// layer-0 buckets only: single short atomic chain (critical for aggregate L0)
__global__ void build0_kernel(const int* __restrict__ ei) {
    int e = blockIdx.x * blockDim.x + threadIdx.x;
    if (e >= E0) return;
    int s0 = ei[e];
    int d0 = ei[E0 + e];
    if (s0 == d0) return;
    int p = atomicAdd(&g_cnt[d0], 1);
    if (p < CAP) g_adj[d0 * CAP + p] = s0;
}

// layer-1/2 dedupe buckets (consumed only by aggregate L1/L2 — off critical path)
__global__ void build12_kernel(const int* __restrict__ ei) {
    int e = blockIdx.x * blockDim.x + threadIdx.x;
    if (e >= E0) return;
    int s0 = ei[e];
    int d0 = ei[E0 + e];
    if (s0 == d0) return;
    int s1 = s0 >> 1, d1 = d0 >> 1;
    if (s1 == d1) return;
    unsigned key1 = (unsigned)s1 * 512u + (unsigned)(d1 & 511);
    unsigned bit1 = 1u << (key1 & 31);
    if (!(atomicOr(&g_bitmap[key1 >> 5], bit1) & bit1)) {
        int p = atomicAdd(&g_cnt[M0 + d1], 1);
        if (p < CAP) g_adj[(M0 + d1) * CAP + p] = s1;
    }
    int s2 = s1 >> 1, d2 = d1 >> 1;
    if (s2 == d2) return;
    unsigned key2 = (unsigned)s2 * 256u + (unsigned)(d2 & 255);
    unsigned bit2 = 1u << (key2 & 31);
    if (!(atomicOr(&g_bitmap[BM0_WORDS + (key2 >> 5)], bit2) & bit2)) {
        int p = atomicAdd(&g_cnt[M0 + M0 / 2 + d2], 1);
        if (p < CAP) g_adj[(M0 + M0 / 2 + d2) * CAP + p] = s2;
    }
}

// ---------------- WMMA bf16x3 GEMM (+BN-on-load, +attention epilogue) ----------------
static constexpr int XLD = 40;    // X tile leading dim (elements)
static constexpr int WLD = 136;   // W tile leading dim (elements)
static constexpr int GEMM_SMEM = 128 * 132 * 4;   // 67584

__device__ __forceinline__ void split_pack(float a, float b, uint32_t& hi, uint32_t& lo) {
    __nv_bfloat16 h0 = __float2bfloat16(a), h1 = __float2bfloat16(b);
    __nv_bfloat16 l0 = __float2bfloat16(a - __bfloat162float(h0));
    __nv_bfloat16 l1 = __float2bfloat16(b - __bfloat162float(h1));
    hi = ((uint32_t)*(uint16_t*)&h1 << 16) | *(uint16_t*)&h0;
    lo = ((uint32_t)*(uint16_t*)&l1 << 16) | *(uint16_t*)&l0;
}

// PRE=true: W already split into whi_g/wlo_g (bf16); else convert from Wf on the fly.
template <int FIN, bool DO_BN, bool PRE>
__global__ void __launch_bounds__(256)
tgemm_att_kernel(const float* __restrict__ Xp, const float* __restrict__ Wf,
                 const __nv_bfloat16* __restrict__ whi_g, const __nv_bfloat16* __restrict__ wlo_g,
                 const float* __restrict__ a_s, const float* __restrict__ a_d,
                 const float* __restrict__ sums, const float* __restrict__ sumsq,
                 float inv_count) {
    extern __shared__ char smem[];
    __shared__ float sAS[128], sAD[128], sMU[128], sIS[128];
    __nv_bfloat16* Xhi = reinterpret_cast<__nv_bfloat16*>(smem);
    __nv_bfloat16* Xlo = Xhi + 128 * XLD;
    __nv_bfloat16* Whi = Xlo + 128 * XLD;
    __nv_bfloat16* Wlo = Whi + 32 * WLD;
    float* stg = reinterpret_cast<float*>(smem);

    int t = threadIdx.x;
    int w = t >> 5;
    int r0 = blockIdx.x * 128;
    const float* X = Xp ? Xp : g_x;

    if (t < 128) {
        sAS[t] = a_s[t];
        sAD[t] = a_d[t];
        if (DO_BN) {
            float mu = sums[t] * inv_count;
            float var = sumsq[t] * inv_count - mu * mu;
            sMU[t] = mu;
            sIS[t] = rsqrtf(var + 1e-5f);
        }
    }
    __syncthreads();

    int wm = w >> 1, wn = w & 1;
    wmma::fragment<wmma::accumulator, 16, 16, 16, float> acc[2][4];
#pragma unroll
    for (int mi = 0; mi < 2; mi++)
#pragma unroll
        for (int ni = 0; ni < 4; ni++) wmma::fill_fragment(acc[mi][ni], 0.f);

    for (int k0 = 0; k0 < FIN; k0 += 32) {
#pragma unroll
        for (int i = 0; i < 4; i++) {
            int e = t + 256 * i;
            int row = e >> 3, c4 = e & 7;
            float4 v = *reinterpret_cast<const float4*>(&X[(size_t)(r0 + row) * FIN + k0 + c4 * 4]);
            if (DO_BN) {
                int cb = k0 + c4 * 4;
                v.x = (v.x - sMU[cb]) * sIS[cb];
                v.y = (v.y - sMU[cb + 1]) * sIS[cb + 1];
                v.z = (v.z - sMU[cb + 2]) * sIS[cb + 2];
                v.w = (v.w - sMU[cb + 3]) * sIS[cb + 3];
            }
            uint32_t h01, l01, h23, l23;
            split_pack(v.x, v.y, h01, l01);
            split_pack(v.z, v.w, h23, l23);
            int idx = row * XLD + c4 * 4;
            *reinterpret_cast<uint32_t*>(&Xhi[idx]) = h01;
            *reinterpret_cast<uint32_t*>(&Xhi[idx + 2]) = h23;
            *reinterpret_cast<uint32_t*>(&Xlo[idx]) = l01;
            *reinterpret_cast<uint32_t*>(&Xlo[idx + 2]) = l23;
        }
        if (PRE) {
#pragma unroll
            for (int i = 0; i < 2; i++) {
                int e = t + 256 * i;
                int r = e >> 4, c8 = e & 15;
                uint4 vh = *reinterpret_cast<const uint4*>(&whi_g[(size_t)(k0 + r) * 128 + c8 * 8]);
                uint4 vl = *reinterpret_cast<const uint4*>(&wlo_g[(size_t)(k0 + r) * 128 + c8 * 8]);
                int idx = r * WLD + c8 * 8;
                *reinterpret_cast<uint4*>(&Whi[idx]) = vh;
                *reinterpret_cast<uint4*>(&Wlo[idx]) = vl;
            }
        } else {
#pragma unroll
            for (int i = 0; i < 4; i++) {
                int e = t + 256 * i;
                int r = e >> 5, c4 = e & 31;
                float4 v = *reinterpret_cast<const float4*>(&Wf[(size_t)(k0 + r) * 128 + c4 * 4]);
                uint32_t h01, l01, h23, l23;
                split_pack(v.x, v.y, h01, l01);
                split_pack(v.z, v.w, h23, l23);
                int idx = r * WLD + c4 * 4;
                *reinterpret_cast<uint32_t*>(&Whi[idx]) = h01;
                *reinterpret_cast<uint32_t*>(&Whi[idx + 2]) = h23;
                *reinterpret_cast<uint32_t*>(&Wlo[idx]) = l01;
                *reinterpret_cast<uint32_t*>(&Wlo[idx + 2]) = l23;
            }
        }
        __syncthreads();

#pragma unroll
        for (int kk = 0; kk < 32; kk += 16) {
            wmma::fragment<wmma::matrix_a, 16, 16, 16, __nv_bfloat16, wmma::row_major> ahi[2], alo[2];
            wmma::fragment<wmma::matrix_b, 16, 16, 16, __nv_bfloat16, wmma::row_major> bhi[4], blo[4];
#pragma unroll
            for (int mi = 0; mi < 2; mi++) {
                const __nv_bfloat16* pa = Xhi + (wm * 32 + mi * 16) * XLD + kk;
                wmma::load_matrix_sync(ahi[mi], pa, XLD);
                wmma::load_matrix_sync(alo[mi], pa + 128 * XLD, XLD);
            }
#pragma unroll
            for (int ni = 0; ni < 4; ni++) {
                const __nv_bfloat16* pb = Whi + kk * WLD + wn * 64 + ni * 16;
                wmma::load_matrix_sync(bhi[ni], pb, WLD);
                wmma::load_matrix_sync(blo[ni], pb + 32 * WLD, WLD);
            }
#pragma unroll
            for (int mi = 0; mi < 2; mi++)
#pragma unroll
                for (int ni = 0; ni < 4; ni++) {
                    wmma::mma_sync(acc[mi][ni], ahi[mi], bhi[ni], acc[mi][ni]);
                    wmma::mma_sync(acc[mi][ni], ahi[mi], blo[ni], acc[mi][ni]);
                    wmma::mma_sync(acc[mi][ni], alo[mi], bhi[ni], acc[mi][ni]);
                }
        }
        __syncthreads();
    }

#pragma unroll
    for (int mi = 0; mi < 2; mi++)
#pragma unroll
        for (int ni = 0; ni < 4; ni++)
            wmma::store_matrix_sync(stg + (wm * 32 + mi * 16) * 132 + wn * 64 + ni * 16,
                                    acc[mi][ni], 132, wmma::mem_row_major);
    __syncthreads();

    if (t < 128) {
        const float4* row4 = reinterpret_cast<const float4*>(stg) + t * 33;
        const float4* as4 = reinterpret_cast<const float4*>(sAS);
        const float4* ad4 = reinterpret_cast<const float4*>(sAD);
        float es = 0.f, ed = 0.f;
#pragma unroll
        for (int c = 0; c < 32; c++) {
            float4 v = row4[c];
            float4 a = as4[c];
            float4 d = ad4[c];
            es += v.x * a.x + v.y * a.y + v.z * a.z + v.w * a.w;
            ed += v.x * d.x + v.y * d.y + v.z * d.z + v.w * d.w;
        }
        g_es[r0 + t] = es;
        g_ed[r0 + t] = ed;
    }
#pragma unroll
    for (int i = 0; i < 16; i++) {
        int e4 = t + 256 * i;
        int row = e4 >> 5, c4 = e4 & 31;
        reinterpret_cast<float4*>(&g_h[(size_t)(r0 + row) * 128])[c4] =
            reinterpret_cast<const float4*>(stg + row * 132)[c4];
    }
}

// ---------------- fused aggregate + pool + bias + relu + BN stats ----------------
__global__ void __launch_bounds__(256) aggregate_pool_kernel(
        int cbase, const float* __restrict__ bias,
        float* __restrict__ sums, float* __restrict__ sumsq) {
    __shared__ int sh_s[8][2 * CAP];
    __shared__ float sh_w[8][2 * CAP];
    __shared__ float psum[8][128];
    __shared__ float psq[8][128];
    int t = threadIdx.x;
    int wp = t >> 5;
    int lane = t & 31;
    int j = blockIdx.x * 8 + wp;
    int a = 2 * j, b = a + 1;

    int na = min(g_cnt[cbase + a], CAP);
    int nb = min(g_cnt[cbase + b], CAP);
    int base_a = (cbase + a) * CAP;
    int base_b = (cbase + b) * CAP;
    float ed_a = g_ed[a], ed_b = g_ed[b];
    float sl_a = lrelu(g_es[a] + ed_a);
    float sl_b = lrelu(g_es[b] + ed_b);

    float mxa = sl_a, mxb = sl_b;
    for (int i = lane; i < na; i += 32) {
        int s = g_adj[base_a + i];
        float lg = lrelu(g_es[s] + ed_a);
        sh_s[wp][i] = s;
        sh_w[wp][i] = lg;
        mxa = fmaxf(mxa, lg);
    }
    for (int i = lane; i < nb; i += 32) {
        int s = g_adj[base_b + i];
        float lg = lrelu(g_es[s] + ed_b);
        sh_s[wp][CAP + i] = s;
        sh_w[wp][CAP + i] = lg;
        mxb = fmaxf(mxb, lg);
    }
#pragma unroll
    for (int o = 16; o; o >>= 1) {
        mxa = fmaxf(mxa, __shfl_xor_sync(0xffffffffu, mxa, o));
        mxb = fmaxf(mxb, __shfl_xor_sync(0xffffffffu, mxb, o));
    }
    __syncwarp();
    for (int i = lane; i < na; i += 32) sh_w[wp][i] = __expf(sh_w[wp][i] - mxa);
    for (int i = lane; i < nb; i += 32) sh_w[wp][CAP + i] = __expf(sh_w[wp][CAP + i] - mxb);
    __syncwarp();

    const float4* h4 = reinterpret_cast<const float4*>(g_h);
    float wsa = __expf(sl_a - mxa);
    float wsb = __expf(sl_b - mxb);
    float4 ha = h4[a * 32 + lane];
    float4 hb = h4[b * 32 + lane];
    float4 accA = make_float4(wsa * ha.x, wsa * ha.y, wsa * ha.z, wsa * ha.w);
    float4 accB = make_float4(wsb * hb.x, wsb * hb.y, wsb * hb.z, wsb * hb.w);
    float denA = wsa, denB = wsb;

    int nc = min(na, nb);
    int k = 0;
#pragma unroll 4
    for (; k < nc; k++) {
        int sA = sh_s[wp][k];
        int sB = sh_s[wp][CAP + k];
        float wA = sh_w[wp][k];
        float wB = sh_w[wp][CAP + k];
        float4 hA = h4[sA * 32 + lane];
        float4 hB = h4[sB * 32 + lane];
        denA += wA; denB += wB;
        accA.x += wA * hA.x; accA.y += wA * hA.y; accA.z += wA * hA.z; accA.w += wA * hA.w;
        accB.x += wB * hB.x; accB.y += wB * hB.y; accB.z += wB * hB.z; accB.w += wB * hB.w;
    }
#pragma unroll 2
    for (; k < na; k++) {
        int sA = sh_s[wp][k];
        float wA = sh_w[wp][k];
        float4 hA = h4[sA * 32 + lane];
        denA += wA;
        accA.x += wA * hA.x; accA.y += wA * hA.y; accA.z += wA * hA.z; accA.w += wA * hA.w;
    }
#pragma unroll 2
    for (; k < nb; k++) {
        int sB = sh_s[wp][CAP + k];
        float wB = sh_w[wp][CAP + k];
        float4 hB = h4[sB * 32 + lane];
        denB += wB;
        accB.x += wB * hB.x; accB.y += wB * hB.y; accB.z += wB * hB.z; accB.w += wB * hB.w;
    }

    float iA = 1.f / denA, iB = 1.f / denB;
    float4 bv = reinterpret_cast<const float4*>(bias)[lane];
    float4 v;
    v.x = fmaxf(fmaxf(accA.x * iA, accB.x * iB) + bv.x, 0.f);
    v.y = fmaxf(fmaxf(accA.y * iA, accB.y * iB) + bv.y, 0.f);
    v.z = fmaxf(fmaxf(accA.z * iA, accB.z * iB) + bv.z, 0.f);
    v.w = fmaxf(fmaxf(accA.w * iA, accB.w * iB) + bv.w, 0.f);
    reinterpret_cast<float4*>(g_x)[j * 32 + lane] = v;

    *reinterpret_cast<float4*>(&psum[wp][lane * 4]) = v;
    *reinterpret_cast<float4*>(&psq[wp][lane * 4]) =
        make_float4(v.x * v.x, v.y * v.y, v.z * v.z, v.w * v.w);
    __syncthreads();
    if (t < 128) {
        float s = 0.f, q = 0.f;
#pragma unroll
        for (int w2 = 0; w2 < 8; w2++) { s += psum[w2][t]; q += psq[w2][t]; }
        atomicAdd(&sums[t], s);
        atomicAdd(&sumsq[t], q);
    }
}

__global__ void bn_apply_kernel(int Mout, float* __restrict__ outp,
                                const float* __restrict__ sums, const float* __restrict__ sumsq) {
    int idx = blockIdx.x * blockDim.x + threadIdx.x;
    if (idx >= Mout * 128) return;
    int c = idx & 127;
    float inv = 1.f / (float)Mout;
    float mu = sums[c] * inv;
    float var = sumsq[c] * inv - mu * mu;
    outp[idx] = (g_x[idx] - mu) * rsqrtf(var + 1e-5f);
}

// ---------------- launch ----------------
extern "C" void kernel_launch(void* const* d_in, const int* in_sizes, int n_in,
                              void* d_out, int out_size) {
    const float* x    = (const float*)d_in[0];
    const float* W0   = (const float*)d_in[1];
    const float* W1   = (const float*)d_in[2];
    const float* W2   = (const float*)d_in[3];
    const float* as_  = (const float*)d_in[4];
    const float* ad_  = (const float*)d_in[5];
    const float* bias = (const float*)d_in[6];
    const int*   ei   = (const int*)d_in[7];
    float* out = (float*)d_out;

    float* sum_p; float* ssq_p;
    cudaGetSymbolAddress((void**)&sum_p, g_sum);
    cudaGetSymbolAddress((void**)&ssq_p, g_sumsq);
    __nv_bfloat16* whi_p; __nv_bfloat16* wlo_p;
    cudaGetSymbolAddress((void**)&whi_p, g_whi);
    cudaGetSymbolAddress((void**)&wlo_p, g_wlo);

    cudaFuncSetAttribute(tgemm_att_kernel<64, false, false>,
                         cudaFuncAttributeMaxDynamicSharedMemorySize, GEMM_SMEM);
    cudaFuncSetAttribute(tgemm_att_kernel<128, true, true>,
                         cudaFuncAttributeMaxDynamicSharedMemorySize, GEMM_SMEM);

    static cudaStream_t sA = nullptr, sB = nullptr;
    static cudaEvent_t e0 = nullptr, eA = nullptr, eW = nullptr, eB = nullptr;
    if (!sA) {
        cudaStreamCreateWithFlags(&sA, cudaStreamNonBlocking);
        cudaStreamCreateWithFlags(&sB, cudaStreamNonBlocking);
        cudaEventCreateWithFlags(&e0, cudaEventDisableTiming);
        cudaEventCreateWithFlags(&eA, cudaEventDisableTiming);
        cudaEventCreateWithFlags(&eW, cudaEventDisableTiming);
        cudaEventCreateWithFlags(&eB, cudaEventDisableTiming);
    }

    // fork both side streams from the main stream
    cudaEventRecord(e0, 0);
    cudaStreamWaitEvent(sA, e0, 0);
    cudaStreamWaitEvent(sB, e0, 0);

    // stream A: layer-0 adjacency (needed by aggregate L0)
    clearA_kernel<<<(M0 + 255) / 256, 256, 0, sA>>>();
    build0_kernel<<<E0 / 256, 256, 0, sA>>>(ei);
    cudaEventRecord(eA, sA);

    // stream B: W pre-split (needed by gemm L1), then layer-1/2 adjacency (needed by agg L1)
    wsplit_kernel<<<(128 * 128) / 256, 256, 0, sB>>>(W1, whi_p, wlo_p);
    wsplit_kernel<<<(128 * 128) / 256, 256, 0, sB>>>(W2, whi_p + 128 * 128, wlo_p + 128 * 128);
    cudaEventRecord(eW, sB);
    clearB_kernel<<<(BM_TOT + 255) / 256, 256, 0, sB>>>();
    build12_kernel<<<E0 / 256, 256, 0, sB>>>(ei);
    cudaEventRecord(eB, sB);

    // layer 0 (W0 converted inline) — runs concurrent with both side streams
    tgemm_att_kernel<64, false, false><<<M0 / 128, 256, GEMM_SMEM>>>(
        x, W0, nullptr, nullptr, as_, ad_, nullptr, nullptr, 0.f);
    cudaStreamWaitEvent(0, eA, 0);
    aggregate_pool_kernel<<<16384 / 8, 256>>>(0, bias, sum_p, ssq_p);

    // layer 1 (pre-split W1)
    cudaStreamWaitEvent(0, eW, 0);
    tgemm_att_kernel<128, true, true><<<16384 / 128, 256, GEMM_SMEM>>>(
        nullptr, nullptr, whi_p, wlo_p, as_ + 128, ad_ + 128, sum_p, ssq_p, 1.f / 16384.f);
    cudaStreamWaitEvent(0, eB, 0);
    aggregate_pool_kernel<<<8192 / 8, 256>>>(M0, bias + 128, sum_p + 128, ssq_p + 128);

    // layer 2 (pre-split W2)
    tgemm_att_kernel<128, true, true><<<8192 / 128, 256, GEMM_SMEM>>>(
        nullptr, nullptr, whi_p + 128 * 128, wlo_p + 128 * 128,
        as_ + 256, ad_ + 256, sum_p + 128, ssq_p + 128, 1.f / 8192.f);
    aggregate_pool_kernel<<<4096 / 8, 256>>>(M0 + M0 / 2, bias + 256, sum_p + 256, ssq_p + 256);

    // final BN -> output
    bn_apply_kernel<<<(4096 * 128) / 256, 256>>>(4096, out, sum_p + 256, ssq_p + 256);
}

// round 17
// speedup vs baseline: 1.4016x; 1.4016x over previous
#include <cuda_runtime.h>
#include <cuda_bf16.h>
#include <mma.h>
#include <math.h>
#include <stdint.h>

using namespace nvcuda;

static constexpr int M0 = 32768;     // B*N nodes at layer 0
static constexpr int E0 = 262144;    // edges
static constexpr int CAP = 96;       // bucket capacity
static constexpr int CNT_TOT = M0 + M0 / 2 + M0 / 4;
static constexpr int BM0_WORDS = (16384 * 512) / 32;
static constexpr int BM1_WORDS = (8192 * 256) / 32;
static constexpr int BM_TOT = BM0_WORDS + BM1_WORDS;

// ---------------- device scratch ----------------
__device__ float g_h[M0 * 128];
__device__ float g_x[(M0 / 2) * 128];
__device__ float g_es[M0];
__device__ float g_ed[M0];
__device__ int g_adj[CNT_TOT * CAP];
__device__ int g_cnt[CNT_TOT];
__device__ unsigned g_bitmap[BM_TOT];
__device__ float g_sum[3][128];
__device__ float g_sumsq[3][128];
__device__ __align__(16) __nv_bfloat16 g_whi[2][128 * 128];   // pre-split W1, W2
__device__ __align__(16) __nv_bfloat16 g_wlo[2][128 * 128];

__device__ __forceinline__ float lrelu(float x) { return x > 0.f ? x : 0.2f * x; }

// ---------------- setup ----------------

// zero layer-0 counters + BN stat slots (short; precedes build0)
__global__ void clearA_kernel() {
    int i = blockIdx.x * blockDim.x + threadIdx.x;
    if (i < M0) g_cnt[i] = 0;
    if (i < 3 * 128) { (&g_sum[0][0])[i] = 0.f; (&g_sumsq[0][0])[i] = 0.f; }
}

// zero bitmaps + layer-1/2 counters (precedes build12; consumed only at agg L1)
__global__ void clearB_kernel() {
    int i = blockIdx.x * blockDim.x + threadIdx.x;
    if (i < BM_TOT) g_bitmap[i] = 0u;
    if (i < CNT_TOT - M0) g_cnt[M0 + i] = 0;
}

__global__ void wsplit_kernel(const float* __restrict__ W,
                              __nv_bfloat16* __restrict__ hi,
                              __nv_bfloat16* __restrict__ lo) {
    int i = blockIdx.x * blockDim.x + threadIdx.x;   // 0..16383
    float v = W[i];
    __nv_bfloat16 h = __float2bfloat16(v);
    hi[i] = h;
    lo[i] = __float2bfloat16(v - __bfloat162float(h));
}

// layer-0 buckets: single short atomic chain (gates aggregate L0)
__global__ void build0_kernel(const int* __restrict__ ei) {
    int e = blockIdx.x * blockDim.x + threadIdx.x;
    if (e >= E0) return;
    int s0 = ei[e];
    int d0 = ei[E0 + e];
    if (s0 == d0) return;
    int p = atomicAdd(&g_cnt[d0], 1);
    if (p < CAP) g_adj[d0 * CAP + p] = s0;
}

// layer-1/2 dedupe buckets (consumed at aggregate L1/L2 — lots of slack)
__global__ void build12_kernel(const int* __restrict__ ei) {
    int e = blockIdx.x * blockDim.x + threadIdx.x;
    if (e >= E0) return;
    int s0 = ei[e];
    int d0 = ei[E0 + e];
    if (s0 == d0) return;
    int s1 = s0 >> 1, d1 = d0 >> 1;
    if (s1 == d1) return;
    unsigned key1 = (unsigned)s1 * 512u + (unsigned)(d1 & 511);
    unsigned bit1 = 1u << (key1 & 31);
    if (!(atomicOr(&g_bitmap[key1 >> 5], bit1) & bit1)) {
        int p = atomicAdd(&g_cnt[M0 + d1], 1);
        if (p < CAP) g_adj[(M0 + d1) * CAP + p] = s1;
    }
    int s2 = s1 >> 1, d2 = d1 >> 1;
    if (s2 == d2) return;
    unsigned key2 = (unsigned)s2 * 256u + (unsigned)(d2 & 255);
    unsigned bit2 = 1u << (key2 & 31);
    if (!(atomicOr(&g_bitmap[BM0_WORDS + (key2 >> 5)], bit2) & bit2)) {
        int p = atomicAdd(&g_cnt[M0 + M0 / 2 + d2], 1);
        if (p < CAP) g_adj[(M0 + M0 / 2 + d2) * CAP + p] = s2;
    }
}

// ---------------- WMMA bf16x3 GEMM (+BN-on-load, +attention epilogue) ----------------
static constexpr int XLD = 40;    // X tile leading dim (elements)
static constexpr int WLD = 136;   // W tile leading dim (elements)
static constexpr int GEMM_SMEM = 128 * 132 * 4;   // 67584

__device__ __forceinline__ void split_pack(float a, float b, uint32_t& hi, uint32_t& lo) {
    __nv_bfloat16 h0 = __float2bfloat16(a), h1 = __float2bfloat16(b);
    __nv_bfloat16 l0 = __float2bfloat16(a - __bfloat162float(h0));
    __nv_bfloat16 l1 = __float2bfloat16(b - __bfloat162float(h1));
    hi = ((uint32_t)*(uint16_t*)&h1 << 16) | *(uint16_t*)&h0;
    lo = ((uint32_t)*(uint16_t*)&l1 << 16) | *(uint16_t*)&l0;
}

// PRE=true: W already split into whi_g/wlo_g (bf16); else convert from Wf on the fly.
template <int FIN, bool DO_BN, bool PRE>
__global__ void __launch_bounds__(256)
tgemm_att_kernel(const float* __restrict__ Xp, const float* __restrict__ Wf,
                 const __nv_bfloat16* __restrict__ whi_g, const __nv_bfloat16* __restrict__ wlo_g,
                 const float* __restrict__ a_s, const float* __restrict__ a_d,
                 const float* __restrict__ sums, const float* __restrict__ sumsq,
                 float inv_count) {
    extern __shared__ char smem[];
    __shared__ float sAS[128], sAD[128], sMU[128], sIS[128];
    __nv_bfloat16* Xhi = reinterpret_cast<__nv_bfloat16*>(smem);
    __nv_bfloat16* Xlo = Xhi + 128 * XLD;
    __nv_bfloat16* Whi = Xlo + 128 * XLD;
    __nv_bfloat16* Wlo = Whi + 32 * WLD;
    float* stg = reinterpret_cast<float*>(smem);

    int t = threadIdx.x;
    int w = t >> 5;
    int r0 = blockIdx.x * 128;
    const float* X = Xp ? Xp : g_x;

    if (t < 128) {
        sAS[t] = a_s[t];
        sAD[t] = a_d[t];
        if (DO_BN) {
            float mu = sums[t] * inv_count;
            float var = sumsq[t] * inv_count - mu * mu;
            sMU[t] = mu;
            sIS[t] = rsqrtf(var + 1e-5f);
        }
    }
    __syncthreads();

    int wm = w >> 1, wn = w & 1;
    wmma::fragment<wmma::accumulator, 16, 16, 16, float> acc[2][4];
#pragma unroll
    for (int mi = 0; mi < 2; mi++)
#pragma unroll
        for (int ni = 0; ni < 4; ni++) wmma::fill_fragment(acc[mi][ni], 0.f);

    for (int k0 = 0; k0 < FIN; k0 += 32) {
#pragma unroll
        for (int i = 0; i < 4; i++) {
            int e = t + 256 * i;
            int row = e >> 3, c4 = e & 7;
            float4 v = *reinterpret_cast<const float4*>(&X[(size_t)(r0 + row) * FIN + k0 + c4 * 4]);
            if (DO_BN) {
                int cb = k0 + c4 * 4;
                v.x = (v.x - sMU[cb]) * sIS[cb];
                v.y = (v.y - sMU[cb + 1]) * sIS[cb + 1];
                v.z = (v.z - sMU[cb + 2]) * sIS[cb + 2];
                v.w = (v.w - sMU[cb + 3]) * sIS[cb + 3];
            }
            uint32_t h01, l01, h23, l23;
            split_pack(v.x, v.y, h01, l01);
            split_pack(v.z, v.w, h23, l23);
            int idx = row * XLD + c4 * 4;
            *reinterpret_cast<uint32_t*>(&Xhi[idx]) = h01;
            *reinterpret_cast<uint32_t*>(&Xhi[idx + 2]) = h23;
            *reinterpret_cast<uint32_t*>(&Xlo[idx]) = l01;
            *reinterpret_cast<uint32_t*>(&Xlo[idx + 2]) = l23;
        }
        if (PRE) {
#pragma unroll
            for (int i = 0; i < 2; i++) {
                int e = t + 256 * i;
                int r = e >> 4, c8 = e & 15;
                uint4 vh = *reinterpret_cast<const uint4*>(&whi_g[(size_t)(k0 + r) * 128 + c8 * 8]);
                uint4 vl = *reinterpret_cast<const uint4*>(&wlo_g[(size_t)(k0 + r) * 128 + c8 * 8]);
                int idx = r * WLD + c8 * 8;
                *reinterpret_cast<uint4*>(&Whi[idx]) = vh;
                *reinterpret_cast<uint4*>(&Wlo[idx]) = vl;
            }
        } else {
#pragma unroll
            for (int i = 0; i < 4; i++) {
                int e = t + 256 * i;
                int r = e >> 5, c4 = e & 31;
                float4 v = *reinterpret_cast<const float4*>(&Wf[(size_t)(k0 + r) * 128 + c4 * 4]);
                uint32_t h01, l01, h23, l23;
                split_pack(v.x, v.y, h01, l01);
                split_pack(v.z, v.w, h23, l23);
                int idx = r * WLD + c4 * 4;
                *reinterpret_cast<uint32_t*>(&Whi[idx]) = h01;
                *reinterpret_cast<uint32_t*>(&Whi[idx + 2]) = h23;
                *reinterpret_cast<uint32_t*>(&Wlo[idx]) = l01;
                *reinterpret_cast<uint32_t*>(&Wlo[idx + 2]) = l23;
            }
        }
        __syncthreads();

#pragma unroll
        for (int kk = 0; kk < 32; kk += 16) {
            wmma::fragment<wmma::matrix_a, 16, 16, 16, __nv_bfloat16, wmma::row_major> ahi[2], alo[2];
            wmma::fragment<wmma::matrix_b, 16, 16, 16, __nv_bfloat16, wmma::row_major> bhi[4], blo[4];
#pragma unroll
            for (int mi = 0; mi < 2; mi++) {
                const __nv_bfloat16* pa = Xhi + (wm * 32 + mi * 16) * XLD + kk;
                wmma::load_matrix_sync(ahi[mi], pa, XLD);
                wmma::load_matrix_sync(alo[mi], pa + 128 * XLD, XLD);
            }
#pragma unroll
            for (int ni = 0; ni < 4; ni++) {
                const __nv_bfloat16* pb = Whi + kk * WLD + wn * 64 + ni * 16;
                wmma::load_matrix_sync(bhi[ni], pb, WLD);
                wmma::load_matrix_sync(blo[ni], pb + 32 * WLD, WLD);
            }
#pragma unroll
            for (int mi = 0; mi < 2; mi++)
#pragma unroll
                for (int ni = 0; ni < 4; ni++) {
                    wmma::mma_sync(acc[mi][ni], ahi[mi], bhi[ni], acc[mi][ni]);
                    wmma::mma_sync(acc[mi][ni], ahi[mi], blo[ni], acc[mi][ni]);
                    wmma::mma_sync(acc[mi][ni], alo[mi], bhi[ni], acc[mi][ni]);
                }
        }
        __syncthreads();
    }

#pragma unroll
    for (int mi = 0; mi < 2; mi++)
#pragma unroll
        for (int ni = 0; ni < 4; ni++)
            wmma::store_matrix_sync(stg + (wm * 32 + mi * 16) * 132 + wn * 64 + ni * 16,
                                    acc[mi][ni], 132, wmma::mem_row_major);
    __syncthreads();

    if (t < 128) {
        const float4* row4 = reinterpret_cast<const float4*>(stg) + t * 33;
        const float4* as4 = reinterpret_cast<const float4*>(sAS);
        const float4* ad4 = reinterpret_cast<const float4*>(sAD);
        float es = 0.f, ed = 0.f;
#pragma unroll
        for (int c = 0; c < 32; c++) {
            float4 v = row4[c];
            float4 a = as4[c];
            float4 d = ad4[c];
            es += v.x * a.x + v.y * a.y + v.z * a.z + v.w * a.w;
            ed += v.x * d.x + v.y * d.y + v.z * d.z + v.w * d.w;
        }
        g_es[r0 + t] = es;
        g_ed[r0 + t] = ed;
    }
#pragma unroll
    for (int i = 0; i < 16; i++) {
        int e4 = t + 256 * i;
        int row = e4 >> 5, c4 = e4 & 31;
        reinterpret_cast<float4*>(&g_h[(size_t)(r0 + row) * 128])[c4] =
            reinterpret_cast<const float4*>(stg + row * 132)[c4];
    }
}

// ---------------- fused aggregate + pool + bias + relu + BN stats ----------------
__global__ void __launch_bounds__(256) aggregate_pool_kernel(
        int cbase, const float* __restrict__ bias,
        float* __restrict__ sums, float* __restrict__ sumsq) {
    __shared__ int sh_s[8][2 * CAP];
    __shared__ float sh_w[8][2 * CAP];
    __shared__ float psum[8][128];
    __shared__ float psq[8][128];
    int t = threadIdx.x;
    int wp = t >> 5;
    int lane = t & 31;
    int j = blockIdx.x * 8 + wp;
    int a = 2 * j, b = a + 1;

    int na = min(g_cnt[cbase + a], CAP);
    int nb = min(g_cnt[cbase + b], CAP);
    int base_a = (cbase + a) * CAP;
    int base_b = (cbase + b) * CAP;
    float ed_a = g_ed[a], ed_b = g_ed[b];
    float sl_a = lrelu(g_es[a] + ed_a);
    float sl_b = lrelu(g_es[b] + ed_b);

    float mxa = sl_a, mxb = sl_b;
    for (int i = lane; i < na; i += 32) {
        int s = g_adj[base_a + i];
        float lg = lrelu(g_es[s] + ed_a);
        sh_s[wp][i] = s;
        sh_w[wp][i] = lg;
        mxa = fmaxf(mxa, lg);
    }
    for (int i = lane; i < nb; i += 32) {
        int s = g_adj[base_b + i];
        float lg = lrelu(g_es[s] + ed_b);
        sh_s[wp][CAP + i] = s;
        sh_w[wp][CAP + i] = lg;
        mxb = fmaxf(mxb, lg);
    }
#pragma unroll
    for (int o = 16; o; o >>= 1) {
        mxa = fmaxf(mxa, __shfl_xor_sync(0xffffffffu, mxa, o));
        mxb = fmaxf(mxb, __shfl_xor_sync(0xffffffffu, mxb, o));
    }
    __syncwarp();
    for (int i = lane; i < na; i += 32) sh_w[wp][i] = __expf(sh_w[wp][i] - mxa);
    for (int i = lane; i < nb; i += 32) sh_w[wp][CAP + i] = __expf(sh_w[wp][CAP + i] - mxb);
    __syncwarp();

    const float4* h4 = reinterpret_cast<const float4*>(g_h);
    float wsa = __expf(sl_a - mxa);
    float wsb = __expf(sl_b - mxb);
    float4 ha = h4[a * 32 + lane];
    float4 hb = h4[b * 32 + lane];
    float4 accA = make_float4(wsa * ha.x, wsa * ha.y, wsa * ha.z, wsa * ha.w);
    float4 accB = make_float4(wsb * hb.x, wsb * hb.y, wsb * hb.z, wsb * hb.w);
    float denA = wsa, denB = wsb;

    int nc = min(na, nb);
    int k = 0;
#pragma unroll 4
    for (; k < nc; k++) {
        int sA = sh_s[wp][k];
        int sB = sh_s[wp][CAP + k];
        float wA = sh_w[wp][k];
        float wB = sh_w[wp][CAP + k];
        float4 hA = h4[sA * 32 + lane];
        float4 hB = h4[sB * 32 + lane];
        denA += wA; denB += wB;
        accA.x += wA * hA.x; accA.y += wA * hA.y; accA.z += wA * hA.z; accA.w += wA * hA.w;
        accB.x += wB * hB.x; accB.y += wB * hB.y; accB.z += wB * hB.z; accB.w += wB * hB.w;
    }
#pragma unroll 2
    for (; k < na; k++) {
        int sA = sh_s[wp][k];
        float wA = sh_w[wp][k];
        float4 hA = h4[sA * 32 + lane];
        denA += wA;
        accA.x += wA * hA.x; accA.y += wA * hA.y; accA.z += wA * hA.z; accA.w += wA * hA.w;
    }
#pragma unroll 2
    for (; k < nb; k++) {
        int sB = sh_s[wp][CAP + k];
        float wB = sh_w[wp][CAP + k];
        float4 hB = h4[sB * 32 + lane];
        denB += wB;
        accB.x += wB * hB.x; accB.y += wB * hB.y; accB.z += wB * hB.z; accB.w += wB * hB.w;
    }

    float iA = 1.f / denA, iB = 1.f / denB;
    float4 bv = reinterpret_cast<const float4*>(bias)[lane];
    float4 v;
    v.x = fmaxf(fmaxf(accA.x * iA, accB.x * iB) + bv.x, 0.f);
    v.y = fmaxf(fmaxf(accA.y * iA, accB.y * iB) + bv.y, 0.f);
    v.z = fmaxf(fmaxf(accA.z * iA, accB.z * iB) + bv.z, 0.f);
    v.w = fmaxf(fmaxf(accA.w * iA, accB.w * iB) + bv.w, 0.f);
    reinterpret_cast<float4*>(g_x)[j * 32 + lane] = v;

    *reinterpret_cast<float4*>(&psum[wp][lane * 4]) = v;
    *reinterpret_cast<float4*>(&psq[wp][lane * 4]) =
        make_float4(v.x * v.x, v.y * v.y, v.z * v.z, v.w * v.w);
    __syncthreads();
    if (t < 128) {
        float s = 0.f, q = 0.f;
#pragma unroll
        for (int w2 = 0; w2 < 8; w2++) { s += psum[w2][t]; q += psq[w2][t]; }
        atomicAdd(&sums[t], s);
        atomicAdd(&sumsq[t], q);
    }
}

__global__ void bn_apply_kernel(int Mout, float* __restrict__ outp,
                                const float* __restrict__ sums, const float* __restrict__ sumsq) {
    int idx = blockIdx.x * blockDim.x + threadIdx.x;
    if (idx >= Mout * 128) return;
    int c = idx & 127;
    float inv = 1.f / (float)Mout;
    float mu = sums[c] * inv;
    float var = sumsq[c] * inv - mu * mu;
    outp[idx] = (g_x[idx] - mu) * rsqrtf(var + 1e-5f);
}

// ---------------- launch ----------------
extern "C" void kernel_launch(void* const* d_in, const int* in_sizes, int n_in,
                              void* d_out, int out_size) {
    const float* x    = (const float*)d_in[0];
    const float* W0   = (const float*)d_in[1];
    const float* W1   = (const float*)d_in[2];
    const float* W2   = (const float*)d_in[3];
    const float* as_  = (const float*)d_in[4];
    const float* ad_  = (const float*)d_in[5];
    const float* bias = (const float*)d_in[6];
    const int*   ei   = (const int*)d_in[7];
    float* out = (float*)d_out;

    float* sum_p; float* ssq_p;
    cudaGetSymbolAddress((void**)&sum_p, g_sum);
    cudaGetSymbolAddress((void**)&ssq_p, g_sumsq);
    __nv_bfloat16* whi_p; __nv_bfloat16* wlo_p;
    cudaGetSymbolAddress((void**)&whi_p, g_whi);
    cudaGetSymbolAddress((void**)&wlo_p, g_wlo);

    cudaFuncSetAttribute(tgemm_att_kernel<64, false, false>,
                         cudaFuncAttributeMaxDynamicSharedMemorySize, GEMM_SMEM);
    cudaFuncSetAttribute(tgemm_att_kernel<128, true, true>,
                         cudaFuncAttributeMaxDynamicSharedMemorySize, GEMM_SMEM);

    // single side stream, same topology as the 113.8us version (R14) —
    // only the ORDER inside the side stream changed (build0 first).
    static cudaStream_t side = nullptr;
    static cudaEvent_t e0 = nullptr, eA = nullptr, eW = nullptr, eB = nullptr;
    if (!side) {
        cudaStreamCreateWithFlags(&side, cudaStreamNonBlocking);
        cudaEventCreateWithFlags(&e0, cudaEventDisableTiming);
        cudaEventCreateWithFlags(&eA, cudaEventDisableTiming);
        cudaEventCreateWithFlags(&eW, cudaEventDisableTiming);
        cudaEventCreateWithFlags(&eB, cudaEventDisableTiming);
    }

    cudaEventRecord(e0, 0);
    cudaStreamWaitEvent(side, e0, 0);

    // side stream: layer-0 adjacency FIRST (gates agg L0), then W split, then L1/2 adjacency
    clearA_kernel<<<(M0 + 255) / 256, 256, 0, side>>>();
    build0_kernel<<<E0 / 256, 256, 0, side>>>(ei);
    cudaEventRecord(eA, side);
    wsplit_kernel<<<(128 * 128) / 256, 256, 0, side>>>(W1, whi_p, wlo_p);
    wsplit_kernel<<<(128 * 128) / 256, 256, 0, side>>>(W2, whi_p + 128 * 128, wlo_p + 128 * 128);
    cudaEventRecord(eW, side);
    clearB_kernel<<<(BM_TOT + 255) / 256, 256, 0, side>>>();
    build12_kernel<<<E0 / 256, 256, 0, side>>>(ei);
    cudaEventRecord(eB, side);

    // layer 0 (W0 converted inline) — concurrent with side stream
    tgemm_att_kernel<64, false, false><<<M0 / 128, 256, GEMM_SMEM>>>(
        x, W0, nullptr, nullptr, as_, ad_, nullptr, nullptr, 0.f);
    cudaStreamWaitEvent(0, eA, 0);
    aggregate_pool_kernel<<<16384 / 8, 256>>>(0, bias, sum_p, ssq_p);

    // layer 1 (pre-split W1)
    cudaStreamWaitEvent(0, eW, 0);
    tgemm_att_kernel<128, true, true><<<16384 / 128, 256, GEMM_SMEM>>>(
        nullptr, nullptr, whi_p, wlo_p, as_ + 128, ad_ + 128, sum_p, ssq_p, 1.f / 16384.f);
    cudaStreamWaitEvent(0, eB, 0);
    aggregate_pool_kernel<<<8192 / 8, 256>>>(M0, bias + 128, sum_p + 128, ssq_p + 128);

    // layer 2 (pre-split W2)
    tgemm_att_kernel<128, true, true><<<8192 / 128, 256, GEMM_SMEM>>>(
        nullptr, nullptr, whi_p + 128 * 128, wlo_p + 128 * 128,
        as_ + 256, ad_ + 256, sum_p + 128, ssq_p + 128, 1.f / 8192.f);
    aggregate_pool_kernel<<<4096 / 8, 256>>>(M0 + M0 / 2, bias + 256, sum_p + 256, ssq_p + 256);

    // final BN -> output
    bn_apply_kernel<<<(4096 * 128) / 256, 256>>>(4096, out, sum_p + 256, ssq_p + 256);
}